// round 12
// baseline (speedup 1.0000x reference)
#include <cuda_runtime.h>
#include <cuda_fp16.h>
#include <cstdint>
#include <cfloat>

// ---------------- problem constants ----------------
#define NB 16
#define NT 1024
#define NF 512
#define NG 2
#define NV 320
#define ND 128
#define NTOK (NB*NT)        // 16384
#define NJ (NG*NV)          // 640

// ---------------- device scratch (no cudaMalloc allowed) ----------------
__device__ __half g_xh[(size_t)NTOK * NF];       // fp16(x)
__device__ __half g_w0[(size_t)NJ * NF];         // fp16(w)
__device__ __half g_w1[(size_t)NJ * NF];         // fp16(w - fp16(w))
__device__ __half g_logits_h[(size_t)NTOK * NJ]; // 20 MB (fp16 logits)
__device__ float g_counts[NT * NG * NV];
__device__ float g_avg[NG * NV];

// ---------------- helpers ----------------
__device__ __forceinline__ uint32_t smem_u32(const void* p) {
    uint32_t a;
    asm("{ .reg .u64 t; cvta.to.shared.u64 t, %1; cvt.u32.u64 %0, t; }" : "=r"(a) : "l"(p));
    return a;
}
#define SW128(b) ((b) ^ (((b) >> 3) & 0x70))
#define CP_ASYNC16(s, g) \
    asm volatile("cp.async.cg.shared.global [%0], [%1], 16;" :: "r"(s), "l"(g))
#define CP_COMMIT() asm volatile("cp.async.commit_group;" ::: "memory")
#define CP_WAIT(n)  asm volatile("cp.async.wait_group %0;" :: "n"(n) : "memory")
#define LDSM_X4(r0, r1, r2, r3, addr) \
    asm volatile("ldmatrix.sync.aligned.m8n8.x4.shared.b16 {%0,%1,%2,%3}, [%4];" \
        : "=r"(r0), "=r"(r1), "=r"(r2), "=r"(r3) : "r"(addr))
#define MMA16816(c, a0, a1, a2, a3, b0, b1) \
    asm volatile("mma.sync.aligned.m16n8k16.row.col.f32.f16.f16.f32 " \
        "{%0,%1,%2,%3}, {%4,%5,%6,%7}, {%8,%9}, {%0,%1,%2,%3};" \
        : "+f"((c)[0]), "+f"((c)[1]), "+f"((c)[2]), "+f"((c)[3]) \
        : "r"(a0), "r"(a1), "r"(a2), "r"(a3), "r"(b0), "r"(b1))

// exact fp32 dot over 512 features, warp-collective; result valid on all lanes
__device__ __forceinline__ float warp_dot512(const float* __restrict__ a,
                                             const float* __restrict__ b, int lane) {
    const float4* a4 = (const float4*)a;
    const float4* b4 = (const float4*)b;
    float s = 0.f;
    #pragma unroll
    for (int u = 0; u < 4; u++) {
        float4 av = a4[lane + u * 32], bv = b4[lane + u * 32];
        s += av.x * bv.x + av.y * bv.y + av.z * bv.z + av.w * bv.w;
    }
    #pragma unroll
    for (int o = 16; o; o >>= 1) s += __shfl_xor_sync(0xffffffffu, s, o);
    return s;
}

// ---------------- split + zero (merged), 2 float4 per thread ----------------
#define X4 (NTOK * NF / 4)   // 2097152
#define W4 (NJ * NF / 4)     // 81920
__global__ __launch_bounds__(256) void split_zero_kernel(
    const float4* __restrict__ xs, const float4* __restrict__ ws,
    float* __restrict__ out_scalars)
{
    int i0 = blockIdx.x * 512 + threadIdx.x;
    #pragma unroll
    for (int k = 0; k < 2; k++) {
        int i = i0 + k * 256;
        if (i < NT * NG * NV) g_counts[i] = 0.f;
        if (i < NG * NV) g_avg[i] = 0.f;
        if (i < 2) out_scalars[i] = 0.f;

        if (i < X4) {
            float4 v = xs[i];
            __half2* d0 = (__half2*)g_xh;
            d0[2*i]   = __halves2half2(__float2half_rn(v.x), __float2half_rn(v.y));
            d0[2*i+1] = __halves2half2(__float2half_rn(v.z), __float2half_rn(v.w));
        } else if (i < X4 + W4) {
            int idx = i - X4;
            float4 v = ws[idx];
            __half hx = __float2half_rn(v.x), hy = __float2half_rn(v.y);
            __half hz = __float2half_rn(v.z), hw = __float2half_rn(v.w);
            float rx = v.x - __half2float(hx), ry = v.y - __half2float(hy);
            float rz = v.z - __half2float(hz), rw = v.w - __half2float(hw);
            __half2* d0 = (__half2*)g_w0;
            __half2* d1 = (__half2*)g_w1;
            d0[2*idx]   = __halves2half2(hx, hy);
            d0[2*idx+1] = __halves2half2(hz, hw);
            d1[2*idx]   = __halves2half2(__float2half_rn(rx), __float2half_rn(ry));
            d1[2*idx+1] = __halves2half2(__float2half_rn(rz), __float2half_rn(rw));
        }
    }
}

// ---------------- HMMA GEMM (proven): fused w0+w1 planes ----------------
#define STAGES 2
#define STG_A 16384
#define STG_B 8192
#define STG_BYTES (STG_A + 2 * STG_B)    // 32768
#define GEMM_SMEM (STAGES * STG_BYTES)   // 65536

__global__ __launch_bounds__(128, 3) void gemm_mma_kernel(const float* __restrict__ bias)
{
    extern __shared__ __align__(1024) char smem[];
    const uint32_t sb = smem_u32(smem);
    const int tid = threadIdx.x, lane = tid & 31, wid = tid >> 5;
    const int wm = (wid & 1) * 64;
    const int wn = (wid >> 1) * 32;
    const int m0 = blockIdx.y * 128;
    const int j0 = blockIdx.x * 64;

    float acc[4][4][4];
    #pragma unroll
    for (int mt = 0; mt < 4; mt++)
        #pragma unroll
        for (int nt = 0; nt < 4; nt++)
            #pragma unroll
            for (int c = 0; c < 4; c++) acc[mt][nt][c] = 0.f;

    auto load_stage = [&](int s, int it) {
        const int kk = it * 64;
        const uint32_t stA = sb + s * STG_BYTES;
        #pragma unroll
        for (int n = 0; n < 8; n++) {
            int i = tid + n * 128;
            int r = i >> 3, u = i & 7;
            CP_ASYNC16(stA + SW128(r * 128 + u * 16),
                       (const void*)(g_xh + (size_t)(m0 + r) * NF + kk + u * 8));
        }
        #pragma unroll
        for (int n = 0; n < 4; n++) {
            int i = tid + n * 128;
            int r = i >> 3, u = i & 7;
            uint32_t so = SW128(r * 128 + u * 16);
            const size_t go = (size_t)(j0 + r) * NF + kk + u * 8;
            CP_ASYNC16(stA + STG_A + so,          (const void*)(g_w0 + go));
            CP_ASYNC16(stA + STG_A + STG_B + so,  (const void*)(g_w1 + go));
        }
        CP_COMMIT();
    };

    load_stage(0, 0);
    load_stage(1, 1);

    for (int it = 0; it < 8; it++) {
        CP_WAIT(1);
        __syncthreads();
        const uint32_t stA = sb + (it & 1) * STG_BYTES;
        #pragma unroll
        for (int ks = 0; ks < 4; ks++) {
            uint32_t a[4][4], b0[2][4], b1[2][4];
            #pragma unroll
            for (int mt = 0; mt < 4; mt++) {
                uint32_t off = (uint32_t)(wm + mt * 16 + (lane & 15)) * 128 + ks * 32 + (lane >> 4) * 16;
                LDSM_X4(a[mt][0], a[mt][1], a[mt][2], a[mt][3], stA + SW128(off));
            }
            #pragma unroll
            for (int nb = 0; nb < 2; nb++) {
                uint32_t off = SW128((uint32_t)(wn + nb * 16 + (lane & 15)) * 128 + ks * 32 + (lane >> 4) * 16);
                LDSM_X4(b0[nb][0], b0[nb][1], b0[nb][2], b0[nb][3], stA + STG_A + off);
                LDSM_X4(b1[nb][0], b1[nb][1], b1[nb][2], b1[nb][3], stA + STG_A + STG_B + off);
            }
            #pragma unroll
            for (int mt = 0; mt < 4; mt++)
                #pragma unroll
                for (int nt = 0; nt < 4; nt++) {
                    MMA16816(acc[mt][nt], a[mt][0], a[mt][1], a[mt][2], a[mt][3],
                             b0[nt >> 1][nt & 1], b0[nt >> 1][(nt & 1) + 2]);
                    MMA16816(acc[mt][nt], a[mt][0], a[mt][1], a[mt][2], a[mt][3],
                             b1[nt >> 1][nt & 1], b1[nt >> 1][(nt & 1) + 2]);
                }
        }
        __syncthreads();
        if (it + 2 < 8) load_stage(it & 1, it + 2);
    }

    #pragma unroll
    for (int mt = 0; mt < 4; mt++) {
        #pragma unroll
        for (int nt = 0; nt < 4; nt++) {
            int row = m0 + wm + mt * 16 + (lane >> 2);
            int col = j0 + wn + nt * 8 + (lane & 3) * 2;
            float2 bv = *(const float2*)(bias + col);
            __half2 h0 = __halves2half2(__float2half_rn(acc[mt][nt][0] + bv.x),
                                        __float2half_rn(acc[mt][nt][1] + bv.y));
            __half2 h1 = __halves2half2(__float2half_rn(acc[mt][nt][2] + bv.x),
                                        __float2half_rn(acc[mt][nt][3] + bv.y));
            *(__half2*)(g_logits_h + (size_t)row * NJ + col) = h0;
            *(__half2*)(g_logits_h + (size_t)(row + 8) * NJ + col) = h1;
        }
    }
}

// ---------------- epilogue: top-2 tracking + cp.async pipeline ----------------
#define DELTA 0.125f
#define BUFB 1920
__global__ __launch_bounds__(256, 5) void epilogue_kernel(
    const float* __restrict__ x, const float* __restrict__ w_proj,
    const float* __restrict__ bias,
    const float* __restrict__ gumbel, const float* __restrict__ codebook,
    float* __restrict__ out)
{
    __shared__ float sAvg[8][NV];                    // 10240 B
    __shared__ __align__(16) char pbuf[8][2][BUFB];  // 30720 B

    const int tid = threadIdx.x;
    const int wid = tid >> 5;
    const int lane = tid & 31;
    const int g = wid & 1;

    for (int i = lane; i < NV; i += 32) sAvg[wid][i] = 0.f;

    auto prefetch = [&](int slot, int task) {
        int n = task >> 1;
        uint32_t dst = smem_u32(&pbuf[wid][slot][0]);
        const char* lsrc = (const char*)(g_logits_h + (size_t)n * NJ + g * NV);
        const char* gsrc = (const char*)(gumbel + (size_t)n * NJ + g * NV);
        #pragma unroll
        for (int c = lane; c < 120; c += 32) {
            if (c < 40) CP_ASYNC16(dst + c * 16, lsrc + c * 16);
            else        CP_ASYNC16(dst + 640 + (c - 40) * 16, gsrc + (size_t)(c - 40) * 16);
        }
        CP_COMMIT();
    };

    const int t0 = blockIdx.x * 32 + wid;
    prefetch(0, t0);
    prefetch(1, t0 + 8);

    for (int it = 0; it < 4; it++) {
        const int task = t0 + it * 8;
        const int slot = it & 1;
        if (it < 3) { CP_WAIT(1); } else { CP_WAIT(0); }
        __syncwarp();

        const int n = task >> 1;
        const __half2* lrow2 = (const __half2*)&pbuf[wid][slot][0];
        const float* grow = (const float*)&pbuf[wid][slot][640];
        const float2* grow2 = (const float2*)grow;

        // ---- top-2 tracking for both argmax targets ----
        float l[10];
        float m1L = -FLT_MAX, m2L = -FLT_MAX; int k1 = 0;
        float m1G = -FLT_MAX, m2G = -FLT_MAX; int k2 = 0;
        #pragma unroll
        for (int i = 0; i < 5; i++) {
            int p = lane + i * 32;
            float2 lv = __half22float2(lrow2[p]);
            float2 gv = grow2[p];
            l[2*i]   = lv.x;
            l[2*i+1] = lv.y;
            int v0 = p * 2;
            if (lv.x > m1L) { m2L = m1L; m1L = lv.x; k1 = v0; }
            else if (lv.x > m2L) m2L = lv.x;
            if (lv.y > m1L) { m2L = m1L; m1L = lv.y; k1 = v0 + 1; }
            else if (lv.y > m2L) m2L = lv.y;
            float g0 = lv.x + gv.x, g1 = lv.y + gv.y;
            if (g0 > m1G) { m2G = m1G; m1G = g0; k2 = v0; }
            else if (g0 > m2G) m2G = g0;
            if (g1 > m1G) { m2G = m1G; m1G = g1; k2 = v0 + 1; }
            else if (g1 > m2G) m2G = g1;
        }
        #pragma unroll
        for (int off = 16; off; off >>= 1) {
            float o1 = __shfl_xor_sync(0xffffffffu, m1L, off);
            float o2 = __shfl_xor_sync(0xffffffffu, m2L, off);
            int   oi = __shfl_xor_sync(0xffffffffu, k1,  off);
            if (o1 > m1L || (o1 == m1L && oi < k1)) {
                m2L = fmaxf(m1L, o2); m1L = o1; k1 = oi;
            } else {
                m2L = fmaxf(m2L, o1);
            }
            float p1 = __shfl_xor_sync(0xffffffffu, m1G, off);
            float p2 = __shfl_xor_sync(0xffffffffu, m2G, off);
            int   pj = __shfl_xor_sync(0xffffffffu, k2,  off);
            if (p1 > m1G || (p1 == m1G && pj < k2)) {
                m2G = fmaxf(m1G, p2); m1G = p1; k2 = pj;
            } else {
                m2G = fmaxf(m2G, p1);
            }
        }

        // ---- exact recheck only when runner-up is within DELTA ----
        if (m2L > m1L - DELTA) {
            const float* xr = x + (size_t)n * NF;
            float be = -FLT_MAX; int bi = 0;
            #pragma unroll 1
            for (int i = 0; i < 5; i++) {
                #pragma unroll
                for (int slot2 = 0; slot2 < 2; slot2++) {
                    unsigned m = __ballot_sync(0xffffffffu, l[2*i+slot2] > m1L - DELTA);
                    while (m) {
                        int src = __ffs(m) - 1; m &= m - 1;
                        int v = (src + i * 32) * 2 + slot2;
                        float e = warp_dot512(xr, w_proj + (size_t)(g * NV + v) * NF, lane)
                                  + bias[g * NV + v];
                        if (e > be || (e == be && v < bi)) { be = e; bi = v; }
                    }
                }
            }
            k1 = bi;
        }
        if (m2G > m1G - DELTA) {
            const float* xr = x + (size_t)n * NF;
            float be = -FLT_MAX; int bi = 0;
            #pragma unroll 1
            for (int i = 0; i < 5; i++) {
                #pragma unroll
                for (int slot2 = 0; slot2 < 2; slot2++) {
                    float2 gv = grow2[lane + i * 32];
                    float lg = l[2*i+slot2] + (slot2 ? gv.y : gv.x);
                    unsigned m = __ballot_sync(0xffffffffu, lg > m1G - DELTA);
                    while (m) {
                        int src = __ffs(m) - 1; m &= m - 1;
                        int v = (src + i * 32) * 2 + slot2;
                        float e = warp_dot512(xr, w_proj + (size_t)(g * NV + v) * NF, lane)
                                  + bias[g * NV + v] + grow[v];
                        if (e > be || (e == be && v < bi)) { be = e; bi = v; }
                    }
                }
            }
            k2 = bi;
        }

        // ---- softmax over approx logits ----
        float s = 0.f;
        #pragma unroll
        for (int i = 0; i < 10; i++) { l[i] = __expf(l[i] - m1L); s += l[i]; }
        #pragma unroll
        for (int off = 16; off; off >>= 1) s += __shfl_xor_sync(0xffffffffu, s, off);
        float inv = 1.0f / s;
        #pragma unroll
        for (int i = 0; i < 5; i++) {
            int v0 = (lane + i * 32) * 2;
            sAvg[wid][v0]     += l[2*i]   * inv;
            sAvg[wid][v0 + 1] += l[2*i+1] * inv;
        }

        if (lane == 0)
            atomicAdd(&g_counts[((n & (NT - 1)) * NG + g) * NV + k1], 1.0f);

        float4 cb = ((const float4*)(codebook + (size_t)(g * NV + k2) * ND))[lane];
        ((float4*)(out + (size_t)n * (NG * ND) + g * ND))[lane] = cb;

        __syncwarp();
        if (it + 2 < 4) prefetch(slot, task + 16);
    }

    __syncthreads();
    for (int xx = tid; xx < NG * NV; xx += 256) {
        int gg = xx / NV, v = xx - gg * NV;
        float s = sAvg[gg][v] + sAvg[gg + 2][v] + sAvg[gg + 4][v] + sAvg[gg + 6][v];
        atomicAdd(&g_avg[xx], s);
    }
}

// ---------------- perplexity reduction: warp-per-row, 8 rows/block ----------------
__global__ __launch_bounds__(256) void perp_kernel(float* __restrict__ out) {
    const int row = blockIdx.x * 8 + (threadIdx.x >> 5);
    const int lane = threadIdx.x & 31;
    if (row >= NT * NG + NG) return;
    const float* vals;
    float scale;
    int slot;
    if (row < NT * NG) { vals = g_counts + (size_t)row * NV; scale = 1.0f / NB; slot = 0; }
    else { vals = g_avg + (size_t)(row - NT * NG) * NV; scale = 1.0f / (float)NTOK; slot = 1; }
    float t = 0.f;
    #pragma unroll
    for (int i = 0; i < 10; i++) {
        float p = vals[lane + i * 32] * scale;
        t += p * __logf(p + 1e-7f);
    }
    #pragma unroll
    for (int off = 16; off; off >>= 1) t += __shfl_xor_sync(0xffffffffu, t, off);
    if (lane == 0) atomicAdd(out + slot, __expf(-t));
}

// ---------------- launch ----------------
extern "C" void kernel_launch(void* const* d_in, const int* in_sizes, int n_in,
                              void* d_out, int out_size)
{
    const float* x        = (const float*)d_in[0];  // (16,1024,512)
    const float* w_proj   = (const float*)d_in[1];  // (640,512)
    const float* b_proj   = (const float*)d_in[2];  // (640)
    const float* codebook = (const float*)d_in[3];  // (1,640,128)
    const float* gumbel   = (const float*)d_in[4];  // (16384,2,320)
    float* out = (float*)d_out;
    float* scalars = out + (out_size - 2);

    cudaFuncSetAttribute(gemm_mma_kernel, cudaFuncAttributeMaxDynamicSharedMemorySize, GEMM_SMEM);

    split_zero_kernel<<<(X4 + W4 + 511) / 512, 256>>>(
        (const float4*)x, (const float4*)w_proj, scalars);

    dim3 ggrid(NJ / 64, NTOK / 128);   // (10, 128) = 1280 CTAs
    gemm_mma_kernel<<<ggrid, 128, GEMM_SMEM>>>(b_proj);

    epilogue_kernel<<<1024, 256>>>(x, w_proj, b_proj, gumbel, codebook, out);

    perp_kernel<<<(NT * NG + NG + 7) / 8, 256>>>(scalars);
}

// round 13
// speedup vs baseline: 1.3340x; 1.3340x over previous
#include <cuda_runtime.h>
#include <cuda_fp16.h>
#include <cstdint>
#include <cfloat>

// ---------------- problem constants ----------------
#define NB 16
#define NT 1024
#define NF 512
#define NG 2
#define NV 320
#define ND 128
#define NTOK (NB*NT)        // 16384
#define NJ (NG*NV)          // 640

// ---------------- device scratch (no cudaMalloc allowed) ----------------
__device__ __half g_xh[(size_t)NTOK * NF];       // fp16(x)
__device__ __half g_w0[(size_t)NJ * NF];         // fp16(w)
__device__ __half g_logits_h[(size_t)NTOK * NJ]; // 20 MB (fp16 logits)
__device__ float g_counts[NT * NG * NV];
__device__ float g_avg[NG * NV];

// ---------------- helpers ----------------
__device__ __forceinline__ uint32_t smem_u32(const void* p) {
    uint32_t a;
    asm("{ .reg .u64 t; cvta.to.shared.u64 t, %1; cvt.u32.u64 %0, t; }" : "=r"(a) : "l"(p));
    return a;
}
#define SW128(b) ((b) ^ (((b) >> 3) & 0x70))
#define CP_ASYNC16(s, g) \
    asm volatile("cp.async.cg.shared.global [%0], [%1], 16;" :: "r"(s), "l"(g))
#define CP_COMMIT() asm volatile("cp.async.commit_group;" ::: "memory")
#define CP_WAIT(n)  asm volatile("cp.async.wait_group %0;" :: "n"(n) : "memory")
#define LDSM_X4(r0, r1, r2, r3, addr) \
    asm volatile("ldmatrix.sync.aligned.m8n8.x4.shared.b16 {%0,%1,%2,%3}, [%4];" \
        : "=r"(r0), "=r"(r1), "=r"(r2), "=r"(r3) : "r"(addr))
#define MMA16816(c, a0, a1, a2, a3, b0, b1) \
    asm volatile("mma.sync.aligned.m16n8k16.row.col.f32.f16.f16.f32 " \
        "{%0,%1,%2,%3}, {%4,%5,%6,%7}, {%8,%9}, {%0,%1,%2,%3};" \
        : "+f"((c)[0]), "+f"((c)[1]), "+f"((c)[2]), "+f"((c)[3]) \
        : "r"(a0), "r"(a1), "r"(a2), "r"(a3), "r"(b0), "r"(b1))

// exact fp32 dot over 512 features, warp-collective; result valid on all lanes
__device__ __forceinline__ float warp_dot512(const float* __restrict__ a,
                                             const float* __restrict__ b, int lane) {
    const float4* a4 = (const float4*)a;
    const float4* b4 = (const float4*)b;
    float s = 0.f;
    #pragma unroll
    for (int u = 0; u < 4; u++) {
        float4 av = a4[lane + u * 32], bv = b4[lane + u * 32];
        s += av.x * bv.x + av.y * bv.y + av.z * bv.z + av.w * bv.w;
    }
    #pragma unroll
    for (int o = 16; o; o >>= 1) s += __shfl_xor_sync(0xffffffffu, s, o);
    return s;
}

// ---------------- split + zero (merged), 2 float4 per thread ----------------
#define X4 (NTOK * NF / 4)   // 2097152
#define W4 (NJ * NF / 4)     // 81920
__global__ __launch_bounds__(256) void split_zero_kernel(
    const float4* __restrict__ xs, const float4* __restrict__ ws,
    float* __restrict__ out_scalars)
{
    int i0 = blockIdx.x * 512 + threadIdx.x;
    #pragma unroll
    for (int k = 0; k < 2; k++) {
        int i = i0 + k * 256;
        if (i < NT * NG * NV) g_counts[i] = 0.f;
        if (i < NG * NV) g_avg[i] = 0.f;
        if (i < 2) out_scalars[i] = 0.f;

        if (i < X4) {
            float4 v = xs[i];
            __half2* d0 = (__half2*)g_xh;
            d0[2*i]   = __halves2half2(__float2half_rn(v.x), __float2half_rn(v.y));
            d0[2*i+1] = __halves2half2(__float2half_rn(v.z), __float2half_rn(v.w));
        } else if (i < X4 + W4) {
            int idx = i - X4;
            float4 v = ws[idx];
            __half2* d0 = (__half2*)g_w0;
            d0[2*idx]   = __halves2half2(__float2half_rn(v.x), __float2half_rn(v.y));
            d0[2*idx+1] = __halves2half2(__float2half_rn(v.z), __float2half_rn(v.w));
        }
    }
}

// ---------------- HMMA GEMM: single fp16 pass (R5 geometry, 8 k-iters) ----------------
// BM=128 BN=64 BK=64(half). 128 threads / 4 warps, warp tile 64x32.
// 3-stage cp.async pipeline, SW128 swizzle, 3 CTAs/SM, 1280 CTAs (2.88 waves).
#define STAGES 3
#define STG_A 16384                 // 128 rows x 128B
#define STG_B 8192                  // 64 rows x 128B
#define STG_BYTES (STG_A + STG_B)   // 24576
#define GEMM_SMEM (STAGES * STG_BYTES)   // 73728

__global__ __launch_bounds__(128, 3) void gemm_mma_kernel(const float* __restrict__ bias)
{
    extern __shared__ __align__(1024) char smem[];
    const uint32_t sb = smem_u32(smem);
    const int tid = threadIdx.x, lane = tid & 31, wid = tid >> 5;
    const int wm = (wid & 1) * 64;
    const int wn = (wid >> 1) * 32;
    const int m0 = blockIdx.y * 128;
    const int j0 = blockIdx.x * 64;

    float acc[4][4][4];
    #pragma unroll
    for (int mt = 0; mt < 4; mt++)
        #pragma unroll
        for (int nt = 0; nt < 4; nt++)
            #pragma unroll
            for (int c = 0; c < 4; c++) acc[mt][nt][c] = 0.f;

    auto load_stage = [&](int s, int it) {
        const int kk = it * 64;
        const uint32_t stA = sb + s * STG_BYTES;
        const uint32_t stB = stA + STG_A;
        #pragma unroll
        for (int n = 0; n < 8; n++) {
            int i = tid + n * 128;
            int r = i >> 3, u = i & 7;
            CP_ASYNC16(stA + SW128(r * 128 + u * 16),
                       (const void*)(g_xh + (size_t)(m0 + r) * NF + kk + u * 8));
        }
        #pragma unroll
        for (int n = 0; n < 4; n++) {
            int i = tid + n * 128;
            int r = i >> 3, u = i & 7;
            CP_ASYNC16(stB + SW128(r * 128 + u * 16),
                       (const void*)(g_w0 + (size_t)(j0 + r) * NF + kk + u * 8));
        }
        CP_COMMIT();
    };

    load_stage(0, 0);
    load_stage(1, 1);

    for (int it = 0; it < 8; it++) {
        CP_WAIT(1);
        __syncthreads();
        const int s = it % STAGES;
        const uint32_t stA = sb + s * STG_BYTES;
        const uint32_t stB = stA + STG_A;
        #pragma unroll
        for (int ks = 0; ks < 4; ks++) {
            uint32_t a[4][4], b[2][4];
            #pragma unroll
            for (int mt = 0; mt < 4; mt++) {
                uint32_t off = (uint32_t)(wm + mt * 16 + (lane & 15)) * 128 + ks * 32 + (lane >> 4) * 16;
                LDSM_X4(a[mt][0], a[mt][1], a[mt][2], a[mt][3], stA + SW128(off));
            }
            #pragma unroll
            for (int nb = 0; nb < 2; nb++) {
                uint32_t off = (uint32_t)(wn + nb * 16 + (lane & 15)) * 128 + ks * 32 + (lane >> 4) * 16;
                LDSM_X4(b[nb][0], b[nb][1], b[nb][2], b[nb][3], stB + SW128(off));
            }
            #pragma unroll
            for (int mt = 0; mt < 4; mt++)
                #pragma unroll
                for (int nt = 0; nt < 4; nt++)
                    MMA16816(acc[mt][nt], a[mt][0], a[mt][1], a[mt][2], a[mt][3],
                             b[nt >> 1][nt & 1], b[nt >> 1][(nt & 1) + 2]);
        }
        __syncthreads();
        if (it + 2 < 8) load_stage((it + 2) % STAGES, it + 2);
    }

    // ---- store: add bias, convert to fp16, write ----
    #pragma unroll
    for (int mt = 0; mt < 4; mt++) {
        #pragma unroll
        for (int nt = 0; nt < 4; nt++) {
            int row = m0 + wm + mt * 16 + (lane >> 2);
            int col = j0 + wn + nt * 8 + (lane & 3) * 2;
            float2 bv = *(const float2*)(bias + col);
            __half2 h0 = __halves2half2(__float2half_rn(acc[mt][nt][0] + bv.x),
                                        __float2half_rn(acc[mt][nt][1] + bv.y));
            __half2 h1 = __halves2half2(__float2half_rn(acc[mt][nt][2] + bv.x),
                                        __float2half_rn(acc[mt][nt][3] + bv.y));
            *(__half2*)(g_logits_h + (size_t)row * NJ + col) = h0;
            *(__half2*)(g_logits_h + (size_t)(row + 8) * NJ + col) = h1;
        }
    }
}

// ---------------- epilogue (R11, proven): ballot counts + cp.async pipeline ----------------
#define DELTA 0.125f
#define BUFB 1920
__global__ __launch_bounds__(256, 5) void epilogue_kernel(
    const float* __restrict__ x, const float* __restrict__ w_proj,
    const float* __restrict__ bias,
    const float* __restrict__ gumbel, const float* __restrict__ codebook,
    float* __restrict__ out)
{
    __shared__ float sAvg[8][NV];                    // 10240 B
    __shared__ __align__(16) char pbuf[8][2][BUFB];  // 30720 B

    const int tid = threadIdx.x;
    const int wid = tid >> 5;
    const int lane = tid & 31;
    const int g = wid & 1;

    for (int i = lane; i < NV; i += 32) sAvg[wid][i] = 0.f;

    auto prefetch = [&](int slot, int task) {
        int n = task >> 1;
        uint32_t dst = smem_u32(&pbuf[wid][slot][0]);
        const char* lsrc = (const char*)(g_logits_h + (size_t)n * NJ + g * NV);
        const char* gsrc = (const char*)(gumbel + (size_t)n * NJ + g * NV);
        #pragma unroll
        for (int c = lane; c < 120; c += 32) {
            if (c < 40) CP_ASYNC16(dst + c * 16, lsrc + c * 16);
            else        CP_ASYNC16(dst + 640 + (c - 40) * 16, gsrc + (size_t)(c - 40) * 16);
        }
        CP_COMMIT();
    };

    const int t0 = blockIdx.x * 32 + wid;
    prefetch(0, t0);
    prefetch(1, t0 + 8);

    for (int it = 0; it < 4; it++) {
        const int task = t0 + it * 8;
        const int slot = it & 1;
        if (it < 3) { CP_WAIT(1); } else { CP_WAIT(0); }
        __syncwarp();

        const int n = task >> 1;
        const __half2* lrow2 = (const __half2*)&pbuf[wid][slot][0];
        const float* grow = (const float*)&pbuf[wid][slot][640];
        const float2* grow2 = (const float2*)grow;

        float l[10];
        float bestL = -FLT_MAX; int k1 = 0;
        float bestG = -FLT_MAX; int k2 = 0;
        #pragma unroll
        for (int i = 0; i < 5; i++) {
            int p = lane + i * 32;
            float2 lv = __half22float2(lrow2[p]);
            float2 gv = grow2[p];
            l[2*i]   = lv.x;
            l[2*i+1] = lv.y;
            int v0 = p * 2;
            if (lv.x > bestL) { bestL = lv.x; k1 = v0; }
            if (lv.y > bestL) { bestL = lv.y; k1 = v0 + 1; }
            float g0 = lv.x + gv.x, g1 = lv.y + gv.y;
            if (g0 > bestG) { bestG = g0; k2 = v0; }
            if (g1 > bestG) { bestG = g1; k2 = v0 + 1; }
        }
        #pragma unroll
        for (int off = 16; off; off >>= 1) {
            float oL = __shfl_xor_sync(0xffffffffu, bestL, off);
            int   oi = __shfl_xor_sync(0xffffffffu, k1,   off);
            if (oL > bestL || (oL == bestL && oi < k1)) { bestL = oL; k1 = oi; }
            float oG = __shfl_xor_sync(0xffffffffu, bestG, off);
            int   oj = __shfl_xor_sync(0xffffffffu, k2,   off);
            if (oG > bestG || (oG == bestG && oj < k2)) { bestG = oG; k2 = oj; }
        }

        int ncl = 0, ncg = 0;
        #pragma unroll
        for (int i = 0; i < 5; i++) {
            int p = lane + i * 32;
            float2 gv = grow2[p];
            ncl += __popc(__ballot_sync(0xffffffffu, l[2*i]   > bestL - DELTA));
            ncl += __popc(__ballot_sync(0xffffffffu, l[2*i+1] > bestL - DELTA));
            ncg += __popc(__ballot_sync(0xffffffffu, l[2*i]   + gv.x > bestG - DELTA));
            ncg += __popc(__ballot_sync(0xffffffffu, l[2*i+1] + gv.y > bestG - DELTA));
        }
        if (ncl > 1) {
            const float* xr = x + (size_t)n * NF;
            float be = -FLT_MAX; int bi = 0;
            #pragma unroll 1
            for (int i = 0; i < 5; i++) {
                #pragma unroll
                for (int slot2 = 0; slot2 < 2; slot2++) {
                    unsigned m = __ballot_sync(0xffffffffu, l[2*i+slot2] > bestL - DELTA);
                    while (m) {
                        int src = __ffs(m) - 1; m &= m - 1;
                        int v = (src + i * 32) * 2 + slot2;
                        float e = warp_dot512(xr, w_proj + (size_t)(g * NV + v) * NF, lane)
                                  + bias[g * NV + v];
                        if (e > be || (e == be && v < bi)) { be = e; bi = v; }
                    }
                }
            }
            k1 = bi;
        }
        if (ncg > 1) {
            const float* xr = x + (size_t)n * NF;
            float be = -FLT_MAX; int bi = 0;
            #pragma unroll 1
            for (int i = 0; i < 5; i++) {
                #pragma unroll
                for (int slot2 = 0; slot2 < 2; slot2++) {
                    float2 gv = grow2[lane + i * 32];
                    float lg = l[2*i+slot2] + (slot2 ? gv.y : gv.x);
                    unsigned m = __ballot_sync(0xffffffffu, lg > bestG - DELTA);
                    while (m) {
                        int src = __ffs(m) - 1; m &= m - 1;
                        int v = (src + i * 32) * 2 + slot2;
                        float e = warp_dot512(xr, w_proj + (size_t)(g * NV + v) * NF, lane)
                                  + bias[g * NV + v] + grow[v];
                        if (e > be || (e == be && v < bi)) { be = e; bi = v; }
                    }
                }
            }
            k2 = bi;
        }

        float s = 0.f;
        #pragma unroll
        for (int i = 0; i < 10; i++) { l[i] = __expf(l[i] - bestL); s += l[i]; }
        #pragma unroll
        for (int off = 16; off; off >>= 1) s += __shfl_xor_sync(0xffffffffu, s, off);
        float inv = 1.0f / s;
        #pragma unroll
        for (int i = 0; i < 5; i++) {
            int v0 = (lane + i * 32) * 2;
            sAvg[wid][v0]     += l[2*i]   * inv;
            sAvg[wid][v0 + 1] += l[2*i+1] * inv;
        }

        if (lane == 0)
            atomicAdd(&g_counts[((n & (NT - 1)) * NG + g) * NV + k1], 1.0f);

        float4 cb = ((const float4*)(codebook + (size_t)(g * NV + k2) * ND))[lane];
        ((float4*)(out + (size_t)n * (NG * ND) + g * ND))[lane] = cb;

        __syncwarp();
        if (it + 2 < 4) prefetch(slot, task + 16);
    }

    __syncthreads();
    for (int xx = tid; xx < NG * NV; xx += 256) {
        int gg = xx / NV, v = xx - gg * NV;
        float s = sAvg[gg][v] + sAvg[gg + 2][v] + sAvg[gg + 4][v] + sAvg[gg + 6][v];
        atomicAdd(&g_avg[xx], s);
    }
}

// ---------------- perplexity reduction: warp-per-row, 8 rows/block ----------------
__global__ __launch_bounds__(256) void perp_kernel(float* __restrict__ out) {
    const int row = blockIdx.x * 8 + (threadIdx.x >> 5);
    const int lane = threadIdx.x & 31;
    if (row >= NT * NG + NG) return;
    const float* vals;
    float scale;
    int slot;
    if (row < NT * NG) { vals = g_counts + (size_t)row * NV; scale = 1.0f / NB; slot = 0; }
    else { vals = g_avg + (size_t)(row - NT * NG) * NV; scale = 1.0f / (float)NTOK; slot = 1; }
    float t = 0.f;
    #pragma unroll
    for (int i = 0; i < 10; i++) {
        float p = vals[lane + i * 32] * scale;
        t += p * __logf(p + 1e-7f);
    }
    #pragma unroll
    for (int off = 16; off; off >>= 1) t += __shfl_xor_sync(0xffffffffu, t, off);
    if (lane == 0) atomicAdd(out + slot, __expf(-t));
}

// ---------------- launch ----------------
extern "C" void kernel_launch(void* const* d_in, const int* in_sizes, int n_in,
                              void* d_out, int out_size)
{
    const float* x        = (const float*)d_in[0];  // (16,1024,512)
    const float* w_proj   = (const float*)d_in[1];  // (640,512)
    const float* b_proj   = (const float*)d_in[2];  // (640)
    const float* codebook = (const float*)d_in[3];  // (1,640,128)
    const float* gumbel   = (const float*)d_in[4];  // (16384,2,320)
    float* out = (float*)d_out;
    float* scalars = out + (out_size - 2);

    cudaFuncSetAttribute(gemm_mma_kernel, cudaFuncAttributeMaxDynamicSharedMemorySize, GEMM_SMEM);

    split_zero_kernel<<<(X4 + W4 + 511) / 512, 256>>>(
        (const float4*)x, (const float4*)w_proj, scalars);

    dim3 ggrid(NJ / 64, NTOK / 128);   // (10, 128) = 1280 CTAs
    gemm_mma_kernel<<<ggrid, 128, GEMM_SMEM>>>(b_proj);

    epilogue_kernel<<<1024, 256>>>(x, w_proj, b_proj, gumbel, codebook, out);

    perp_kernel<<<(NT * NG + NG + 7) / 8, 256>>>(scalars);
}

// round 14
// speedup vs baseline: 1.3421x; 1.0060x over previous
#include <cuda_runtime.h>
#include <cuda_fp16.h>
#include <cstdint>
#include <cfloat>

// ---------------- problem constants ----------------
#define NB 16
#define NT 1024
#define NF 512
#define NG 2
#define NV 320
#define ND 128
#define NTOK (NB*NT)        // 16384
#define NJ (NG*NV)          // 640

// ---------------- device scratch (no cudaMalloc allowed) ----------------
__device__ __half g_xh[(size_t)NTOK * NF];       // fp16(x)
__device__ __half g_w0[(size_t)NJ * NF];         // fp16(w)
__device__ __half g_logits_h[(size_t)NTOK * NJ]; // 20 MB (fp16 logits)
__device__ float g_counts[NT * NG * NV];
__device__ float g_avg[NG * NV];

// ---------------- helpers ----------------
__device__ __forceinline__ uint32_t smem_u32(const void* p) {
    uint32_t a;
    asm("{ .reg .u64 t; cvta.to.shared.u64 t, %1; cvt.u32.u64 %0, t; }" : "=r"(a) : "l"(p));
    return a;
}
#define SW128(b) ((b) ^ (((b) >> 3) & 0x70))
#define CP_ASYNC16(s, g) \
    asm volatile("cp.async.cg.shared.global [%0], [%1], 16;" :: "r"(s), "l"(g))
#define CP_COMMIT() asm volatile("cp.async.commit_group;" ::: "memory")
#define CP_WAIT(n)  asm volatile("cp.async.wait_group %0;" :: "n"(n) : "memory")
#define LDSM_X4(r0, r1, r2, r3, addr) \
    asm volatile("ldmatrix.sync.aligned.m8n8.x4.shared.b16 {%0,%1,%2,%3}, [%4];" \
        : "=r"(r0), "=r"(r1), "=r"(r2), "=r"(r3) : "r"(addr))
#define MMA16816(c, a0, a1, a2, a3, b0, b1) \
    asm volatile("mma.sync.aligned.m16n8k16.row.col.f32.f16.f16.f32 " \
        "{%0,%1,%2,%3}, {%4,%5,%6,%7}, {%8,%9}, {%0,%1,%2,%3};" \
        : "+f"((c)[0]), "+f"((c)[1]), "+f"((c)[2]), "+f"((c)[3]) \
        : "r"(a0), "r"(a1), "r"(a2), "r"(a3), "r"(b0), "r"(b1))

// exact fp32 dot over 512 features, warp-collective; result valid on all lanes
__device__ __forceinline__ float warp_dot512(const float* __restrict__ a,
                                             const float* __restrict__ b, int lane) {
    const float4* a4 = (const float4*)a;
    const float4* b4 = (const float4*)b;
    float s = 0.f;
    #pragma unroll
    for (int u = 0; u < 4; u++) {
        float4 av = a4[lane + u * 32], bv = b4[lane + u * 32];
        s += av.x * bv.x + av.y * bv.y + av.z * bv.z + av.w * bv.w;
    }
    #pragma unroll
    for (int o = 16; o; o >>= 1) s += __shfl_xor_sync(0xffffffffu, s, o);
    return s;
}

// ---------------- split + zero (merged), 4 float4 per thread ----------------
#define X4 (NTOK * NF / 4)   // 2097152
#define W4 (NJ * NF / 4)     // 81920
__global__ __launch_bounds__(256) void split_zero_kernel(
    const float4* __restrict__ xs, const float4* __restrict__ ws,
    float* __restrict__ out_scalars)
{
    int i0 = blockIdx.x * 1024 + threadIdx.x;
    #pragma unroll
    for (int k = 0; k < 4; k++) {
        int i = i0 + k * 256;
        if (i < NT * NG * NV) g_counts[i] = 0.f;
        if (i < NG * NV) g_avg[i] = 0.f;
        if (i < 2) out_scalars[i] = 0.f;

        if (i < X4) {
            float4 v = xs[i];
            __half2* d0 = (__half2*)g_xh;
            d0[2*i]   = __halves2half2(__float2half_rn(v.x), __float2half_rn(v.y));
            d0[2*i+1] = __halves2half2(__float2half_rn(v.z), __float2half_rn(v.w));
        } else if (i < X4 + W4) {
            int idx = i - X4;
            float4 v = ws[idx];
            __half2* d0 = (__half2*)g_w0;
            d0[2*idx]   = __halves2half2(__float2half_rn(v.x), __float2half_rn(v.y));
            d0[2*idx+1] = __halves2half2(__float2half_rn(v.z), __float2half_rn(v.w));
        }
    }
}

// ---------------- HMMA GEMM: single fp16 pass (proven R13) ----------------
#define STAGES 3
#define STG_A 16384                 // 128 rows x 128B
#define STG_B 8192                  // 64 rows x 128B
#define STG_BYTES (STG_A + STG_B)   // 24576
#define GEMM_SMEM (STAGES * STG_BYTES)   // 73728

__global__ __launch_bounds__(128, 3) void gemm_mma_kernel(const float* __restrict__ bias)
{
    extern __shared__ __align__(1024) char smem[];
    const uint32_t sb = smem_u32(smem);
    const int tid = threadIdx.x, lane = tid & 31, wid = tid >> 5;
    const int wm = (wid & 1) * 64;
    const int wn = (wid >> 1) * 32;
    const int m0 = blockIdx.y * 128;
    const int j0 = blockIdx.x * 64;

    float acc[4][4][4];
    #pragma unroll
    for (int mt = 0; mt < 4; mt++)
        #pragma unroll
        for (int nt = 0; nt < 4; nt++)
            #pragma unroll
            for (int c = 0; c < 4; c++) acc[mt][nt][c] = 0.f;

    auto load_stage = [&](int s, int it) {
        const int kk = it * 64;
        const uint32_t stA = sb + s * STG_BYTES;
        const uint32_t stB = stA + STG_A;
        #pragma unroll
        for (int n = 0; n < 8; n++) {
            int i = tid + n * 128;
            int r = i >> 3, u = i & 7;
            CP_ASYNC16(stA + SW128(r * 128 + u * 16),
                       (const void*)(g_xh + (size_t)(m0 + r) * NF + kk + u * 8));
        }
        #pragma unroll
        for (int n = 0; n < 4; n++) {
            int i = tid + n * 128;
            int r = i >> 3, u = i & 7;
            CP_ASYNC16(stB + SW128(r * 128 + u * 16),
                       (const void*)(g_w0 + (size_t)(j0 + r) * NF + kk + u * 8));
        }
        CP_COMMIT();
    };

    load_stage(0, 0);
    load_stage(1, 1);

    for (int it = 0; it < 8; it++) {
        CP_WAIT(1);
        __syncthreads();
        const int s = it % STAGES;
        const uint32_t stA = sb + s * STG_BYTES;
        const uint32_t stB = stA + STG_A;
        #pragma unroll
        for (int ks = 0; ks < 4; ks++) {
            uint32_t a[4][4], b[2][4];
            #pragma unroll
            for (int mt = 0; mt < 4; mt++) {
                uint32_t off = (uint32_t)(wm + mt * 16 + (lane & 15)) * 128 + ks * 32 + (lane >> 4) * 16;
                LDSM_X4(a[mt][0], a[mt][1], a[mt][2], a[mt][3], stA + SW128(off));
            }
            #pragma unroll
            for (int nb = 0; nb < 2; nb++) {
                uint32_t off = (uint32_t)(wn + nb * 16 + (lane & 15)) * 128 + ks * 32 + (lane >> 4) * 16;
                LDSM_X4(b[nb][0], b[nb][1], b[nb][2], b[nb][3], stB + SW128(off));
            }
            #pragma unroll
            for (int mt = 0; mt < 4; mt++)
                #pragma unroll
                for (int nt = 0; nt < 4; nt++)
                    MMA16816(acc[mt][nt], a[mt][0], a[mt][1], a[mt][2], a[mt][3],
                             b[nt >> 1][nt & 1], b[nt >> 1][(nt & 1) + 2]);
        }
        __syncthreads();
        if (it + 2 < 8) load_stage((it + 2) % STAGES, it + 2);
    }

    #pragma unroll
    for (int mt = 0; mt < 4; mt++) {
        #pragma unroll
        for (int nt = 0; nt < 4; nt++) {
            int row = m0 + wm + mt * 16 + (lane >> 2);
            int col = j0 + wn + nt * 8 + (lane & 3) * 2;
            float2 bv = *(const float2*)(bias + col);
            __half2 h0 = __halves2half2(__float2half_rn(acc[mt][nt][0] + bv.x),
                                        __float2half_rn(acc[mt][nt][1] + bv.y));
            __half2 h1 = __halves2half2(__float2half_rn(acc[mt][nt][2] + bv.x),
                                        __float2half_rn(acc[mt][nt][3] + bv.y));
            *(__half2*)(g_logits_h + (size_t)row * NJ + col) = h0;
            *(__half2*)(g_logits_h + (size_t)(row + 8) * NJ + col) = h1;
        }
    }
}

// ---------------- epilogue: redux-key argmax + lean candidate test ----------------
#define DELTA 0.125f
#define BUFB 1920
__global__ __launch_bounds__(256, 5) void epilogue_kernel(
    const float* __restrict__ x, const float* __restrict__ w_proj,
    const float* __restrict__ bias,
    const float* __restrict__ gumbel, const float* __restrict__ codebook,
    float* __restrict__ out)
{
    __shared__ float sAvg[8][NV];                    // 10240 B
    __shared__ __align__(16) char pbuf[8][2][BUFB];  // 30720 B

    const int tid = threadIdx.x;
    const int wid = tid >> 5;
    const int lane = tid & 31;
    const int g = wid & 1;

    for (int i = lane; i < NV; i += 32) sAvg[wid][i] = 0.f;

    auto prefetch = [&](int slot, int task) {
        int n = task >> 1;
        uint32_t dst = smem_u32(&pbuf[wid][slot][0]);
        const char* lsrc = (const char*)(g_logits_h + (size_t)n * NJ + g * NV);
        const char* gsrc = (const char*)(gumbel + (size_t)n * NJ + g * NV);
        #pragma unroll
        for (int c = lane; c < 120; c += 32) {
            if (c < 40) CP_ASYNC16(dst + c * 16, lsrc + c * 16);
            else        CP_ASYNC16(dst + 640 + (c - 40) * 16, gsrc + (size_t)(c - 40) * 16);
        }
        CP_COMMIT();
    };

    const int t0 = blockIdx.x * 32 + wid;
    prefetch(0, t0);
    prefetch(1, t0 + 8);

    for (int it = 0; it < 4; it++) {
        const int task = t0 + it * 8;
        const int slot = it & 1;
        if (it < 3) { CP_WAIT(1); } else { CP_WAIT(0); }
        __syncwarp();

        const int n = task >> 1;
        const __half2* lrow2 = (const __half2*)&pbuf[wid][slot][0];
        const float* grow = (const float*)&pbuf[wid][slot][640];
        const float2* grow2 = (const float2*)grow;

        // ---- lane-local scan (proven fast form) ----
        float l[10];
        float bestL = -FLT_MAX; int k1 = 0;
        float bestG = -FLT_MAX; int k2 = 0;
        #pragma unroll
        for (int i = 0; i < 5; i++) {
            int p = lane + i * 32;
            float2 lv = __half22float2(lrow2[p]);
            float2 gv = grow2[p];
            l[2*i]   = lv.x;
            l[2*i+1] = lv.y;
            int v0 = p * 2;
            if (lv.x > bestL) { bestL = lv.x; k1 = v0; }
            if (lv.y > bestL) { bestL = lv.y; k1 = v0 + 1; }
            float g0 = lv.x + gv.x, g1 = lv.y + gv.y;
            if (g0 > bestG) { bestG = g0; k2 = v0; }
            if (g1 > bestG) { bestG = g1; k2 = v0 + 1; }
        }

        // ---- warp argmax via sortable-key redux (L exact fp16; G top-22-bit) ----
        {
            unsigned hb = __half_as_ushort(__float2half_rn(bestL));   // exact round-trip
            unsigned mL = hb ^ ((hb & 0x8000u) ? 0xFFFFu : 0x8000u);
            unsigned keyL = (mL << 16) | (unsigned)(1023 - k1);
            keyL = __reduce_max_sync(0xffffffffu, keyL);
            k1 = 1023 - (int)(keyL & 0xFFFFu);
            unsigned m = keyL >> 16;
            unsigned short b = (m & 0x8000u) ? (unsigned short)(m ^ 0x8000u)
                                             : (unsigned short)(m ^ 0xFFFFu);
            bestL = __half2float(__ushort_as_half(b));
        }
        {
            unsigned ug = __float_as_uint(bestG);
            unsigned mG = ug ^ ((unsigned)((int)ug >> 31) | 0x80000000u);
            unsigned keyG = (mG & 0xFFFFFC00u) | (unsigned)(1023 - k2);
            keyG = __reduce_max_sync(0xffffffffu, keyG);
            k2 = 1023 - (int)(keyG & 0x3FFu);
            unsigned m = (keyG & 0xFFFFFC00u) | 0x200u;
            unsigned b = (m & 0x80000000u) ? (m ^ 0x80000000u) : ~m;
            bestG = __uint_as_float(b);
        }

        // ---- candidate test: per-lane fp counts + 4 ballots ----
        const float thL = bestL - DELTA;
        const float thG = bestG - DELTA - 0.01f;   // margin for keyG quantization
        int cl = 0, cg = 0;
        #pragma unroll
        for (int i = 0; i < 5; i++) {
            float2 gv = grow2[lane + i * 32];
            cl += (l[2*i] > thL) + (l[2*i+1] > thL);
            cg += (l[2*i] + gv.x > thG) + (l[2*i+1] + gv.y > thG);
        }
        unsigned bl1 = __ballot_sync(0xffffffffu, cl > 0);
        unsigned bl2 = __ballot_sync(0xffffffffu, cl > 1);
        unsigned bg1 = __ballot_sync(0xffffffffu, cg > 0);
        unsigned bg2 = __ballot_sync(0xffffffffu, cg > 1);

        if (__popc(bl1) > 1 || bl2) {
            const float* xr = x + (size_t)n * NF;
            float be = -FLT_MAX; int bi = 0;
            #pragma unroll 1
            for (int i = 0; i < 5; i++) {
                #pragma unroll
                for (int slot2 = 0; slot2 < 2; slot2++) {
                    unsigned m = __ballot_sync(0xffffffffu, l[2*i+slot2] > thL);
                    while (m) {
                        int src = __ffs(m) - 1; m &= m - 1;
                        int v = (src + i * 32) * 2 + slot2;
                        float e = warp_dot512(xr, w_proj + (size_t)(g * NV + v) * NF, lane)
                                  + bias[g * NV + v];
                        if (e > be || (e == be && v < bi)) { be = e; bi = v; }
                    }
                }
            }
            k1 = bi;
        }
        if (__popc(bg1) > 1 || bg2) {
            const float* xr = x + (size_t)n * NF;
            float be = -FLT_MAX; int bi = 0;
            #pragma unroll 1
            for (int i = 0; i < 5; i++) {
                #pragma unroll
                for (int slot2 = 0; slot2 < 2; slot2++) {
                    float2 gv = grow2[lane + i * 32];
                    float lg = l[2*i+slot2] + (slot2 ? gv.y : gv.x);
                    unsigned m = __ballot_sync(0xffffffffu, lg > thG);
                    while (m) {
                        int src = __ffs(m) - 1; m &= m - 1;
                        int v = (src + i * 32) * 2 + slot2;
                        float e = warp_dot512(xr, w_proj + (size_t)(g * NV + v) * NF, lane)
                                  + bias[g * NV + v] + grow[v];
                        if (e > be || (e == be && v < bi)) { be = e; bi = v; }
                    }
                }
            }
            k2 = bi;
        }

        // ---- softmax over approx logits ----
        float s = 0.f;
        #pragma unroll
        for (int i = 0; i < 10; i++) { l[i] = __expf(l[i] - bestL); s += l[i]; }
        #pragma unroll
        for (int off = 16; off; off >>= 1) s += __shfl_xor_sync(0xffffffffu, s, off);
        float inv = 1.0f / s;
        #pragma unroll
        for (int i = 0; i < 5; i++) {
            int v0 = (lane + i * 32) * 2;
            sAvg[wid][v0]     += l[2*i]   * inv;
            sAvg[wid][v0 + 1] += l[2*i+1] * inv;
        }

        if (lane == 0)
            atomicAdd(&g_counts[((n & (NT - 1)) * NG + g) * NV + k1], 1.0f);

        float4 cb = ((const float4*)(codebook + (size_t)(g * NV + k2) * ND))[lane];
        ((float4*)(out + (size_t)n * (NG * ND) + g * ND))[lane] = cb;

        __syncwarp();
        if (it + 2 < 4) prefetch(slot, task + 16);
    }

    __syncthreads();
    for (int xx = tid; xx < NG * NV; xx += 256) {
        int gg = xx / NV, v = xx - gg * NV;
        float s = sAvg[gg][v] + sAvg[gg + 2][v] + sAvg[gg + 4][v] + sAvg[gg + 6][v];
        atomicAdd(&g_avg[xx], s);
    }
}

// ---------------- perplexity reduction: warp-per-row, float4 loads ----------------
__global__ __launch_bounds__(256) void perp_kernel(float* __restrict__ out) {
    const int row = blockIdx.x * 8 + (threadIdx.x >> 5);
    const int lane = threadIdx.x & 31;
    if (row >= NT * NG + NG) return;
    const float* vals;
    float scale;
    int slot;
    if (row < NT * NG) { vals = g_counts + (size_t)row * NV; scale = 1.0f / NB; slot = 0; }
    else { vals = g_avg + (size_t)(row - NT * NG) * NV; scale = 1.0f / (float)NTOK; slot = 1; }
    const float4* v4 = (const float4*)vals;
    float t = 0.f;
    #pragma unroll
    for (int i = 0; i < 2; i++) {
        float4 q = v4[lane + i * 32];
        float p0 = q.x * scale, p1 = q.y * scale, p2 = q.z * scale, p3 = q.w * scale;
        t += p0 * __logf(p0 + 1e-7f) + p1 * __logf(p1 + 1e-7f)
           + p2 * __logf(p2 + 1e-7f) + p3 * __logf(p3 + 1e-7f);
    }
    if (lane < 16) {
        float4 q = v4[lane + 64];
        float p0 = q.x * scale, p1 = q.y * scale, p2 = q.z * scale, p3 = q.w * scale;
        t += p0 * __logf(p0 + 1e-7f) + p1 * __logf(p1 + 1e-7f)
           + p2 * __logf(p2 + 1e-7f) + p3 * __logf(p3 + 1e-7f);
    }
    #pragma unroll
    for (int off = 16; off; off >>= 1) t += __shfl_xor_sync(0xffffffffu, t, off);
    if (lane == 0) atomicAdd(out + slot, __expf(-t));
}

// ---------------- launch ----------------
extern "C" void kernel_launch(void* const* d_in, const int* in_sizes, int n_in,
                              void* d_out, int out_size)
{
    const float* x        = (const float*)d_in[0];  // (16,1024,512)
    const float* w_proj   = (const float*)d_in[1];  // (640,512)
    const float* b_proj   = (const float*)d_in[2];  // (640)
    const float* codebook = (const float*)d_in[3];  // (1,640,128)
    const float* gumbel   = (const float*)d_in[4];  // (16384,2,320)
    float* out = (float*)d_out;
    float* scalars = out + (out_size - 2);

    cudaFuncSetAttribute(gemm_mma_kernel, cudaFuncAttributeMaxDynamicSharedMemorySize, GEMM_SMEM);

    split_zero_kernel<<<(X4 + W4 + 1023) / 1024, 256>>>(
        (const float4*)x, (const float4*)w_proj, scalars);

    dim3 ggrid(NJ / 64, NTOK / 128);   // (10, 128) = 1280 CTAs
    gemm_mma_kernel<<<ggrid, 128, GEMM_SMEM>>>(b_proj);

    epilogue_kernel<<<1024, 256>>>(x, w_proj, b_proj, gumbel, codebook, out);

    perp_kernel<<<(NT * NG + NG + 7) / 8, 256>>>(scalars);
}